// round 17
// baseline (speedup 1.0000x reference)
#include <cuda_runtime.h>
#include <cuda_bf16.h>
#include <cstdint>

// GRU_66314295050287 on GB300 (sm_103a) — R17: address-sequential loads.
// Diagnosis: all f-chunked variants sweep each 48KB block region 8x in
// strided 192B pieces (~8x DRAM row activations) -> pinned at ~53% DRAM.
// Fix: chunk = 4 COMPLETE seqs = 6KB contiguous gmem, one pass, in order.
// Compute: intra-warp f-split — lane 8s+q: seq s of group, f in [4q,4q+4);
// partial gates reduced via shfl_xor(1,2,4), routed to owner lane by shfl.
// 32-thread blocks, 8 groups, NBUF=2, grid 2048, 16 blocks/SM (single wave).

#define T_DIM        12
#define FE_DIM       32
#define SEQ_PER_BLK  32
#define NTHREADS     32
#define GROUP_SEQS   4
#define NGROUPS      8                            // 32/4
#define GROUP_FLOATS (GROUP_SEQS * 384)           // 1536 floats = 6 KB
#define GROUP_VEC4   (GROUP_FLOATS / 4)           // 384 float4 -> 12 per lane
#define QPAD         52                           // 48 data floats + 4 pad
#define SEQ_ROW      (8 * QPAD)                   // 416 floats per seq
#define BUF_FLOATS   (GROUP_SEQS * SEQ_ROW)       // 1664 floats per buffer
#define NBUF         2

__device__ __forceinline__ float fast_sigmoid(float x) {
    return 1.0f / (1.0f + __expf(-x));
}
__device__ __forceinline__ float fast_tanh(float x) {
    float e = __expf(2.0f * x);
    return 1.0f - 2.0f / (1.0f + e);
}

__device__ __forceinline__ void cp_async16(unsigned int saddr, const void* gptr) {
    asm volatile("cp.async.cg.shared.global [%0], [%1], 16;\n" :: "r"(saddr), "l"(gptr));
}
__device__ __forceinline__ void cp_commit() {
    asm volatile("cp.async.commit_group;\n");
}
template <int N>
__device__ __forceinline__ void cp_wait() {
    asm volatile("cp.async.wait_group %0;\n" :: "n"(N));
}

extern __shared__ float smem[];

__global__ void __launch_bounds__(NTHREADS, 14)
gru_kernel(const float* __restrict__ x,
           const float* __restrict__ w_ih,   // [3][32]
           const float* __restrict__ w_hh,   // [3][1]
           const float* __restrict__ b_ih,   // [3]
           const float* __restrict__ b_hh,   // [3]
           const float* __restrict__ lin_w,  // [3][12]
           const float* __restrict__ lin_b,  // [3]
           float* __restrict__ out)          // [M][3]
{
    float* sdata = smem;                        // NBUF x BUF_FLOATS
    float* s_wih = smem + NBUF * BUF_FLOATS;    // 96
    float* s_lw  = s_wih + 96;                  // 36

    const int tid = threadIdx.x;
    const int sl  = tid >> 3;                   // group-local seq 0..3
    const int q   = tid & 7;                    // f-eighth: f in [4q, 4q+4)

#pragma unroll
    for (int i = tid; i < 96; i += NTHREADS) s_wih[i] = w_ih[i];
#pragma unroll
    for (int i = tid; i < 36; i += NTHREADS) s_lw[i] = lin_w[i];

    const int m0 = blockIdx.x * SEQ_PER_BLK;
    const unsigned int sbase = (unsigned int)__cvta_generic_to_shared(sdata);

    // Issue group g (seqs m0+4g..m0+4g+3): 6 KB CONTIGUOUS gmem, ascending
    // order (12 float4 per lane, consecutive lanes on consecutive float4).
    // Smem side scatters into the quarter-padded layout.
    auto issue_group = [&](int g, int b) {
        const float4* gbase = reinterpret_cast<const float4*>(x + (long)(m0 + 4 * g) * 384);
#pragma unroll
        for (int k = 0; k < GROUP_VEC4 / NTHREADS; ++k) {
            int i  = k * NTHREADS + tid;        // float4 index in group
            int o  = i * 4;                     // float offset in group
            int sg = o / 384;                   // seq within group
            int u  = o - sg * 384;              // float within seq
            int f  = u / 12;
            int r  = u - f * 12;
            unsigned int dst = sbase +
                (unsigned int)((b * BUF_FLOATS + sg * SEQ_ROW +
                                (f >> 2) * QPAD + (f & 3) * 12 + r) * 4);
            cp_async16(dst, (const void*)(gbase + i));
        }
        cp_commit();
    };

    // Owner-lane gate accumulators (lane l owns seq m0+l), bias folded in.
    float og0[T_DIM], og1[T_DIM], og2[T_DIM];
    {
        const float bi0 = b_ih[0], bi1 = b_ih[1], bi2 = b_ih[2];
#pragma unroll
        for (int t = 0; t < T_DIM; ++t) { og0[t] = bi0; og1[t] = bi1; og2[t] = bi2; }
    }

    issue_group(0, 0);

#pragma unroll
    for (int g = 0; g < NGROUPS; ++g) {
        if (g + 1 < NGROUPS) {
            issue_group(g + 1, (g + 1) & 1);
            cp_wait<1>();           // group g landed; g+1 in flight
        } else {
            cp_wait<0>();
        }
        __syncthreads();            // 1-warp block: BAR floor; group g visible

        // Partial gates for THIS group: seq sl, f in [4q, 4q+4).
        float wk0[T_DIM], wk1[T_DIM], wk2[T_DIM];
#pragma unroll
        for (int t = 0; t < T_DIM; ++t) { wk0[t] = 0.0f; wk1[t] = 0.0f; wk2[t] = 0.0f; }

        const float* my = sdata + (g & 1) * BUF_FLOATS + sl * SEQ_ROW + q * QPAD;
#pragma unroll
        for (int fl = 0; fl < 4; ++fl) {
            int f = q * 4 + fl;
            float w0 = s_wih[f];
            float w1 = s_wih[32 + f];
            float w2 = s_wih[64 + f];
#pragma unroll
            for (int v = 0; v < 3; ++v) {
                float4 a = reinterpret_cast<const float4*>(my + fl * T_DIM)[v];
                int tb = v * 4;
                wk0[tb+0] = fmaf(a.x, w0, wk0[tb+0]);
                wk1[tb+0] = fmaf(a.x, w1, wk1[tb+0]);
                wk2[tb+0] = fmaf(a.x, w2, wk2[tb+0]);
                wk0[tb+1] = fmaf(a.y, w0, wk0[tb+1]);
                wk1[tb+1] = fmaf(a.y, w1, wk1[tb+1]);
                wk2[tb+1] = fmaf(a.y, w2, wk2[tb+1]);
                wk0[tb+2] = fmaf(a.z, w0, wk0[tb+2]);
                wk1[tb+2] = fmaf(a.z, w1, wk1[tb+2]);
                wk2[tb+2] = fmaf(a.z, w2, wk2[tb+2]);
                wk0[tb+3] = fmaf(a.w, w0, wk0[tb+3]);
                wk1[tb+3] = fmaf(a.w, w1, wk1[tb+3]);
                wk2[tb+3] = fmaf(a.w, w2, wk2[tb+3]);
            }
        }
        __syncthreads();            // group g consumed -> buffer refillable

        // Reduce over the 8 f-lanes of each seq (xor 1,2,4), then route the
        // full gates for seq 4g+s' (on lane 8s') to owner lane 4g+s'.
        const int src  = (8 * (tid - 4 * g)) & 31;
        const bool own = (tid >= 4 * g) && (tid < 4 * g + 4);
#pragma unroll
        for (int t = 0; t < T_DIM; ++t) {
            float a0 = wk0[t], a1 = wk1[t], a2 = wk2[t];
            a0 += __shfl_xor_sync(0xffffffffu, a0, 1);
            a1 += __shfl_xor_sync(0xffffffffu, a1, 1);
            a2 += __shfl_xor_sync(0xffffffffu, a2, 1);
            a0 += __shfl_xor_sync(0xffffffffu, a0, 2);
            a1 += __shfl_xor_sync(0xffffffffu, a1, 2);
            a2 += __shfl_xor_sync(0xffffffffu, a2, 2);
            a0 += __shfl_xor_sync(0xffffffffu, a0, 4);
            a1 += __shfl_xor_sync(0xffffffffu, a1, 4);
            a2 += __shfl_xor_sync(0xffffffffu, a2, 4);
            float v0 = __shfl_sync(0xffffffffu, a0, src);
            float v1 = __shfl_sync(0xffffffffu, a1, src);
            float v2 = __shfl_sync(0xffffffffu, a2, src);
            if (own) { og0[t] += v0; og1[t] += v1; og2[t] += v2; }
        }
    }

    // Scalar-hidden GRU recurrence + relu + linear head (lane l = seq m0+l).
    const float wh0 = w_hh[0], wh1 = w_hh[1], wh2 = w_hh[2];
    const float bh0 = b_hh[0], bh1 = b_hh[1], bh2 = b_hh[2];
    float o0 = lin_b[0], o1 = lin_b[1], o2 = lin_b[2];
    float h = 0.0f;
#pragma unroll
    for (int t = 0; t < T_DIM; ++t) {
        float r = fast_sigmoid(og0[t] + wh0 * h + bh0);
        float z = fast_sigmoid(og1[t] + wh1 * h + bh1);
        float n = fast_tanh(og2[t] + r * (wh2 * h + bh2));
        h = (1.0f - z) * n + z * h;
        float hr = fmaxf(h, 0.0f);
        o0 = fmaf(hr, s_lw[t],       o0);
        o1 = fmaf(hr, s_lw[12 + t],  o1);
        o2 = fmaf(hr, s_lw[24 + t],  o2);
    }

    // Coalesced epilogue: stage [32][3] floats, write 24 float4.
    float* s_out = sdata;           // trailing barrier above covered final reads
    s_out[tid * 3 + 0] = o0;        // stride 3 coprime with 32 -> conflict-free
    s_out[tid * 3 + 1] = o1;
    s_out[tid * 3 + 2] = o2;
    __syncthreads();
    if (tid < (SEQ_PER_BLK * 3) / 4) {
        reinterpret_cast<float4*>(out + (long)m0 * 3)[tid] =
            reinterpret_cast<const float4*>(s_out)[tid];
    }
}

extern "C" void kernel_launch(void* const* d_in, const int* in_sizes, int n_in,
                              void* d_out, int out_size) {
    const float* x     = (const float*)d_in[0];
    const float* w_ih  = (const float*)d_in[1];
    const float* w_hh  = (const float*)d_in[2];
    const float* b_ih  = (const float*)d_in[3];
    const float* b_hh  = (const float*)d_in[4];
    const float* lin_w = (const float*)d_in[5];
    const float* lin_b = (const float*)d_in[6];
    float* out = (float*)d_out;

    const int M = in_sizes[0] / (FE_DIM * T_DIM);   // 65536
    const int grid = M / SEQ_PER_BLK;               // 2048

    const size_t smem_bytes = (size_t)(NBUF * BUF_FLOATS + 96 + 36) * sizeof(float);
    cudaFuncSetAttribute(gru_kernel, cudaFuncAttributeMaxDynamicSharedMemorySize,
                         (int)smem_bytes);

    gru_kernel<<<grid, NTHREADS, smem_bytes>>>(x, w_ih, w_hh, b_ih, b_hh,
                                               lin_w, lin_b, out);
}